// round 3
// baseline (speedup 1.0000x reference)
#include <cuda_runtime.h>
#include <math.h>

// Shapes (fixed by the problem)
//  B=32, L=512, T=4096, E=F=256, NB=256
// Inputs (metadata order):
//  0 hidden [B,L,E] f32; 1 mask [B,L] bool; 2 frame_mask [B,T] bool;
//  3 duration_target [B,L] i32; 4 pitch_target [B,T] f32; 5 energy_target [B,T] f32;
//  6 duration_scale scalar int; 7 pred_w1 [3,3,E,F]; 8 pred_b1 [3,F];
//  9 ln1_s; 10 ln1_b; 11 pred_w2 [3,3,F,F]; 12 pred_b2; 13 ln2_s; 14 ln2_b;
//  15 lin_w [3,F]; 16 lin_b [3]; 17 pitch_bins [NB]; 18 pitch_emb [NB,E];
//  19 energy_bins [NB]; 20 energy_emb [NB,E]
// Output: concat(rounded_duration[B*L], pitch[B*T], energy[B*T], variance_embedding[B*T*E])

// -------- scratch (device globals; no allocs allowed) --------
__device__ float g_X [33554432];   // [B,T,E] length-regulated x (later x+pitch_emb)
__device__ float g_H1[33554432];   // predictor hidden 1
__device__ float g_H2[33554432];   // predictor hidden 2
__device__ int   g_cs[16384];      // cumsum durations [B,L]

// ==================== conv(k=3) as implicit-im2col GEMM ====================
// out[b,t,n] = relu(bias[n] + sum_{kk,c} in[b,t+kk-1,c] * W[(kk*256+c)*256+n])
// Tiles: BM=128 tokens, BN=128 outs, BK=16, 256 threads, 8x8 microtile,
// fp32x2 packed FMA with A duplicated pairwise in smem.
#define BM 128
#define BN 128
#define BK 16
#define NKT 48   // 768/16

__device__ __forceinline__ void cg_load(const float* __restrict__ inb,
                                        const float* __restrict__ W,
                                        int S, int t0, int n0, int kt, int tid,
                                        float4 av[2], float4 bv[2]) {
    int kc = kt * BK;
    int kk = kc >> 8;        // conv tap 0..2 (chunk never crosses a tap)
    int c0 = kc & 255;       // channel base within tap
    #pragma unroll
    for (int it = 0; it < 2; it++) {
        int idx = tid + it * 256;
        int m = idx >> 2, v = idx & 3;
        int t = t0 + m + kk - 1;
        float4 a = make_float4(0.f, 0.f, 0.f, 0.f);
        if (t >= 0 && t < S)
            a = *(const float4*)(inb + (size_t)t * 256 + c0 + v * 4);
        av[it] = a;
        int k = idx >> 5, nv = idx & 31;
        bv[it] = *(const float4*)(W + (size_t)(kc + k) * 256 + n0 + nv * 4);
    }
}

__device__ __forceinline__ void cg_store(float* As, float* Bs, int tid,
                                         const float4 av[2], const float4 bv[2]) {
    #pragma unroll
    for (int it = 0; it < 2; it++) {
        int idx = tid + it * 256;
        int m = idx >> 2, v = idx & 3;
        float vals[4] = {av[it].x, av[it].y, av[it].z, av[it].w};
        #pragma unroll
        for (int w = 0; w < 4; w++) {
            // duplicated store: logical row m occupies cols [2m, 2m+1]
            *(float2*)&As[(v * 4 + w) * 256 + 2 * m] = make_float2(vals[w], vals[w]);
        }
        int k = idx >> 5, nv = idx & 31;
        *(float4*)&Bs[k * BN + nv * 4] = bv[it];
    }
}

union U64F2 { unsigned long long u; float2 f; };

__device__ __forceinline__ void cg_compute(const float* As, const float* Bs,
                                           int ty, int tx,
                                           unsigned long long acc[8][4]) {
    #pragma unroll
    for (int k = 0; k < BK; k++) {
        const float* ar = As + k * 256 + 16 * ty;        // 8 dup'd rows = 16 floats
        ulonglong2 q0 = *(const ulonglong2*)(ar + 0);
        ulonglong2 q1 = *(const ulonglong2*)(ar + 4);
        ulonglong2 q2 = *(const ulonglong2*)(ar + 8);
        ulonglong2 q3 = *(const ulonglong2*)(ar + 12);
        unsigned long long a8[8] = {q0.x, q0.y, q1.x, q1.y, q2.x, q2.y, q3.x, q3.y};
        const float* br = Bs + k * BN + 8 * tx;          // 8 cols = 4 col-pairs
        ulonglong2 p0 = *(const ulonglong2*)(br + 0);
        ulonglong2 p1 = *(const ulonglong2*)(br + 4);
        unsigned long long b4[4] = {p0.x, p0.y, p1.x, p1.y};
        #pragma unroll
        for (int i = 0; i < 8; i++)
            #pragma unroll
            for (int j = 0; j < 4; j++)
                asm("fma.rn.f32x2 %0, %1, %2, %0;"
                    : "+l"(acc[i][j]) : "l"(a8[i]), "l"(b4[j]));
    }
}

__global__ __launch_bounds__(256) void conv_gemm_kernel(
    const float* __restrict__ in, const float* __restrict__ W,
    const float* __restrict__ bias, float* __restrict__ out, int S)
{
    __shared__ float sm[12288];     // exactly 48KB: 2 x (A 16x256 dup + B 16x128)
    float* As0 = sm;
    float* Bs0 = sm + 4096;
    float* As1 = sm + 6144;
    float* Bs1 = sm + 10240;

    int tid = threadIdx.x;
    int m0 = blockIdx.x * BM;
    int b  = m0 / S;                // tiles never cross batch boundary (S%128==0)
    int t0 = m0 - b * S;
    int n0 = blockIdx.y * BN;
    int ty = tid >> 4, tx = tid & 15;
    const float* inb = in + (size_t)b * S * 256;

    unsigned long long acc[8][4];
    #pragma unroll
    for (int i = 0; i < 8; i++)
        #pragma unroll
        for (int j = 0; j < 4; j++) acc[i][j] = 0ull;

    float4 av[2], bv[2];
    cg_load(inb, W, S, t0, n0, 0, tid, av, bv);
    cg_store(As0, Bs0, tid, av, bv);
    __syncthreads();

    for (int kt = 0; kt < NKT; kt++) {
        const float* Ac = (kt & 1) ? As1 : As0;
        const float* Bc = (kt & 1) ? Bs1 : Bs0;
        float* An = (kt & 1) ? As0 : As1;
        float* Bn = (kt & 1) ? Bs0 : Bs1;
        if (kt + 1 < NKT) cg_load(inb, W, S, t0, n0, kt + 1, tid, av, bv);
        cg_compute(Ac, Bc, ty, tx, acc);
        if (kt + 1 < NKT) cg_store(An, Bn, tid, av, bv);
        __syncthreads();
    }

    const float* bp = bias + n0 + 8 * tx;
    float bs8[8];
    #pragma unroll
    for (int j = 0; j < 8; j++) bs8[j] = bp[j];

    #pragma unroll
    for (int i = 0; i < 8; i++) {
        int t = t0 + 8 * ty + i;
        float* orow = out + ((size_t)b * S + t) * 256 + n0 + 8 * tx;
        float o[8];
        #pragma unroll
        for (int j = 0; j < 4; j++) {
            U64F2 c; c.u = acc[i][j];
            o[2 * j]     = c.f.x;
            o[2 * j + 1] = c.f.y;
        }
        #pragma unroll
        for (int j = 0; j < 8; j++) o[j] = fmaxf(o[j] + bs8[j], 0.f);
        *(float4*)(orow)     = make_float4(o[0], o[1], o[2], o[3]);
        *(float4*)(orow + 4) = make_float4(o[4], o[5], o[6], o[7]);
    }
}

// ==================== LayerNorm (warp per token, F=256) ====================
__global__ void ln_kernel(float* __restrict__ h, const float* __restrict__ sc,
                          const float* __restrict__ bi, int ntok)
{
    int w = threadIdx.x >> 5, lane = threadIdx.x & 31;
    int t = blockIdx.x * 8 + w;
    if (t >= ntok) return;
    float* row = h + (size_t)t * 256;
    float4 v0 = *(float4*)(row + lane * 4);
    float4 v1 = *(float4*)(row + 128 + lane * 4);
    float s = v0.x + v0.y + v0.z + v0.w + v1.x + v1.y + v1.z + v1.w;
    float q = v0.x*v0.x + v0.y*v0.y + v0.z*v0.z + v0.w*v0.w
            + v1.x*v1.x + v1.y*v1.y + v1.z*v1.z + v1.w*v1.w;
    #pragma unroll
    for (int o = 16; o; o >>= 1) {
        s += __shfl_xor_sync(0xffffffffu, s, o);
        q += __shfl_xor_sync(0xffffffffu, q, o);
    }
    float m   = s * (1.f / 256.f);
    float var = q * (1.f / 256.f) - m * m;
    float r   = rsqrtf(var + 1e-5f);
    int f0 = lane * 4, f1 = 128 + lane * 4;
    float4 s0 = *(const float4*)(sc + f0), s1 = *(const float4*)(sc + f1);
    float4 b0 = *(const float4*)(bi + f0), b1 = *(const float4*)(bi + f1);
    v0.x = (v0.x - m) * r * s0.x + b0.x;  v0.y = (v0.y - m) * r * s0.y + b0.y;
    v0.z = (v0.z - m) * r * s0.z + b0.z;  v0.w = (v0.w - m) * r * s0.w + b0.w;
    v1.x = (v1.x - m) * r * s1.x + b1.x;  v1.y = (v1.y - m) * r * s1.y + b1.y;
    v1.z = (v1.z - m) * r * s1.z + b1.z;  v1.w = (v1.w - m) * r * s1.w + b1.w;
    *(float4*)(row + lane * 4)       = v0;
    *(float4*)(row + 128 + lane * 4) = v1;
}

// ==================== linear F->1 + mask (warp per token) ====================
__device__ __forceinline__ float warp_dot256(const float* row, const float* lw, int lane) {
    float4 v0 = *(const float4*)(row + lane * 4);
    float4 v1 = *(const float4*)(row + 128 + lane * 4);
    float4 w0 = *(const float4*)(lw + lane * 4);
    float4 w1 = *(const float4*)(lw + 128 + lane * 4);
    float d = v0.x*w0.x + v0.y*w0.y + v0.z*w0.z + v0.w*w0.w
            + v1.x*w1.x + v1.y*w1.y + v1.z*w1.z + v1.w*w1.w;
    #pragma unroll
    for (int o = 16; o; o >>= 1) d += __shfl_xor_sync(0xffffffffu, d, o);
    return d;
}

__global__ void linear_mask_kernel(const float* __restrict__ h, const float* __restrict__ lw,
                                   const float* __restrict__ lb,
                                   const unsigned char* __restrict__ mask,
                                   float* __restrict__ out, int ntok)
{
    int w = threadIdx.x >> 5, lane = threadIdx.x & 31;
    int t = blockIdx.x * 8 + w;
    if (t >= ntok) return;
    float d = warp_dot256(h + (size_t)t * 256, lw, lane);
    if (lane == 0) {
        float val = d + lb[0];
        if (mask[t]) val = 0.f;
        out[t] = val;
    }
}

__global__ void dur_final_kernel(const float* __restrict__ h, const float* __restrict__ lw,
                                 const float* __restrict__ lb,
                                 const unsigned char* __restrict__ mask,
                                 const int* __restrict__ scale,
                                 float* __restrict__ out, int ntok)
{
    int w = threadIdx.x >> 5, lane = threadIdx.x & 31;
    int t = blockIdx.x * 8 + w;
    if (t >= ntok) return;
    float d = warp_dot256(h + (size_t)t * 256, lw, lane);
    if (lane == 0) {
        float val = d + lb[0];
        if (mask[t]) val = 0.f;
        float rd = fmaxf(rintf(expf(val) * (float)(*scale)), 0.f);
        out[t] = rd;
    }
}

// ==================== duration cumsum (per-batch inclusive scan) ====================
__global__ void cumsum_kernel(const int* __restrict__ dur, int* __restrict__ cs)
{
    __shared__ int s[512];
    int b = blockIdx.x, t = threadIdx.x;
    s[t] = dur[b * 512 + t];
    __syncthreads();
    for (int off = 1; off < 512; off <<= 1) {
        int v = (t >= off) ? s[t - off] : 0;
        __syncthreads();
        s[t] += v;
        __syncthreads();
    }
    cs[b * 512 + t] = s[t];
}

// ==================== length regulate: X[b,t,:] = hidden[b, idx(t), :] ====================
__global__ void length_reg_kernel(const float* __restrict__ hidden,
                                  const int* __restrict__ cs,
                                  float* __restrict__ X)
{
    __shared__ int scs[512];
    int tid = threadIdx.x;
    int base = blockIdx.x * 4;          // global token index, 4 tokens/block
    int b    = base >> 12;              // /4096
    int tloc = base & 4095;
    const int* csb = cs + b * 512;
    scs[tid]       = csb[tid];
    scs[tid + 256] = csb[tid + 256];
    __syncthreads();
    int g = tid >> 6, lane = tid & 63;
    int t = tloc + g;
    // searchsorted(cs, t, 'right'): first idx with cs[idx] > t
    int lo = 0, hi = 512;
    while (lo < hi) { int mid = (lo + hi) >> 1; if (scs[mid] <= t) lo = mid + 1; else hi = mid; }
    int idx = lo < 512 ? lo : 511;
    bool valid = t < scs[511];
    float4 v = make_float4(0.f, 0.f, 0.f, 0.f);
    if (valid) v = *(const float4*)(hidden + ((size_t)b * 512 + idx) * 256 + lane * 4);
    *(float4*)(X + ((size_t)b * 4096 + t) * 256 + lane * 4) = v;
}

// ==================== bucketize + embedding add ====================
__global__ void add_emb_kernel(const float* __restrict__ X, const float* __restrict__ tgt,
                               const float* __restrict__ bins, const float* __restrict__ emb,
                               float* __restrict__ outp, int ntok)
{
    __shared__ float sb[256];
    int tid = threadIdx.x;
    sb[tid] = bins[tid];
    __syncthreads();
    int base = blockIdx.x * 4;
    int g = tid >> 6, lane = tid & 63;
    int t = base + g;
    if (t >= ntok) return;
    float v = tgt[t];
    // searchsorted(bins, v, 'left'): first idx with bins[idx] >= v, clip to NB-1
    int lo = 0, hi = 256;
    while (lo < hi) { int mid = (lo + hi) >> 1; if (sb[mid] < v) lo = mid + 1; else hi = mid; }
    int idx = lo < 256 ? lo : 255;
    float4 a = *(const float4*)(X + (size_t)t * 256 + lane * 4);
    float4 e = *(const float4*)(emb + (size_t)idx * 256 + lane * 4);
    a.x += e.x; a.y += e.y; a.z += e.z; a.w += e.w;
    *(float4*)(outp + (size_t)t * 256 + lane * 4) = a;
}

// ==================== launch ====================
extern "C" void kernel_launch(void* const* d_in, const int* in_sizes, int n_in,
                              void* d_out, int out_size)
{
    const float*         hidden    = (const float*)d_in[0];
    const unsigned char* mask      = (const unsigned char*)d_in[1];
    const unsigned char* fmask     = (const unsigned char*)d_in[2];
    const int*           dur_tgt   = (const int*)d_in[3];
    const float*         pitch_tgt = (const float*)d_in[4];
    const float*         energy_tgt= (const float*)d_in[5];
    const int*           dscale    = (const int*)d_in[6];
    const float*         w1        = (const float*)d_in[7];
    const float*         b1        = (const float*)d_in[8];
    const float*         l1s       = (const float*)d_in[9];
    const float*         l1b       = (const float*)d_in[10];
    const float*         w2        = (const float*)d_in[11];
    const float*         b2        = (const float*)d_in[12];
    const float*         l2s       = (const float*)d_in[13];
    const float*         l2b       = (const float*)d_in[14];
    const float*         lw        = (const float*)d_in[15];
    const float*         lb        = (const float*)d_in[16];
    const float*         pbins     = (const float*)d_in[17];
    const float*         pemb      = (const float*)d_in[18];
    const float*         ebins     = (const float*)d_in[19];
    const float*         eemb      = (const float*)d_in[20];

    float* X;  float* H1;  float* H2;  int* cs;
    cudaGetSymbolAddress((void**)&X,  g_X);
    cudaGetSymbolAddress((void**)&H1, g_H1);
    cudaGetSymbolAddress((void**)&H2, g_H2);
    cudaGetSymbolAddress((void**)&cs, g_cs);

    float* out_rd     = (float*)d_out;            // [B*L]
    float* out_pitch  = out_rd + 32 * 512;        // [B*T]
    float* out_energy = out_pitch + 32 * 4096;    // [B*T]
    float* out_ve     = out_energy + 32 * 4096;   // [B*T*E]

    const int WSTR = 3 * 256 * 256;               // per-predictor conv weight stride

    // ---- duration predictor on hidden (S=512, ntok=16384) ----
    {
        dim3 g(16384 / 128, 2);
        conv_gemm_kernel<<<g, 256>>>(hidden, w1, b1, H1, 512);
        ln_kernel<<<16384 / 8, 256>>>(H1, l1s, l1b, 16384);
        conv_gemm_kernel<<<g, 256>>>(H1, w2, b2, H2, 512);
        ln_kernel<<<16384 / 8, 256>>>(H2, l2s, l2b, 16384);
        dur_final_kernel<<<16384 / 8, 256>>>(H2, lw, lb, mask, dscale, out_rd, 16384);
    }

    // ---- length regulate ----
    cumsum_kernel<<<32, 512>>>(dur_tgt, cs);
    length_reg_kernel<<<32 * 4096 / 4, 256>>>(hidden, cs, X);

    // ---- pitch predictor on X (S=4096, ntok=131072) ----
    {
        dim3 g(131072 / 128, 2);
        conv_gemm_kernel<<<g, 256>>>(X, w1 + WSTR, b1 + 256, H1, 4096);
        ln_kernel<<<131072 / 8, 256>>>(H1, l1s + 256, l1b + 256, 131072);
        conv_gemm_kernel<<<g, 256>>>(H1, w2 + WSTR, b2 + 256, H2, 4096);
        ln_kernel<<<131072 / 8, 256>>>(H2, l2s + 256, l2b + 256, 131072);
        linear_mask_kernel<<<131072 / 8, 256>>>(H2, lw + 256, lb + 1, fmask, out_pitch, 131072);
    }
    // X += pitch_emb[bucket(pitch_target)]
    add_emb_kernel<<<131072 / 4, 256>>>(X, pitch_tgt, pbins, pemb, X, 131072);

    // ---- energy predictor on X (S=4096) ----
    {
        dim3 g(131072 / 128, 2);
        conv_gemm_kernel<<<g, 256>>>(X, w1 + 2 * WSTR, b1 + 512, H1, 4096);
        ln_kernel<<<131072 / 8, 256>>>(H1, l1s + 512, l1b + 512, 131072);
        conv_gemm_kernel<<<g, 256>>>(H1, w2 + 2 * WSTR, b2 + 512, H2, 4096);
        ln_kernel<<<131072 / 8, 256>>>(H2, l2s + 512, l2b + 512, 131072);
        linear_mask_kernel<<<131072 / 8, 256>>>(H2, lw + 512, lb + 2, fmask, out_energy, 131072);
    }
    // variance_embedding = X + energy_emb[bucket(energy_target)]
    add_emb_kernel<<<131072 / 4, 256>>>(X, energy_tgt, ebins, eemb, out_ve, 131072);
}

// round 6
// speedup vs baseline: 1.8970x; 1.8970x over previous
#include <cuda_runtime.h>
#include <cuda_bf16.h>
#include <math.h>
#include <stdint.h>

typedef __nv_bfloat16 bf16;

// B=32, L=512, T=4096, E=F=256, NB=256
// Output: concat(rounded_duration[B*L], pitch[B*T], energy[B*T], variance_embedding[B*T*E])

// -------- scratch (device globals) --------
__device__ float g_X   [33554432];   // [B,T,E] fp32 length-regulated x (exact path)
__device__ bf16  g_Xhi [33554432];   // hi/lo bf16 split of X
__device__ bf16  g_Xlo [33554432];
__device__ bf16  g_H1hi[33554432];   // hidden1 (post conv1+relu, then LN in-place)
__device__ bf16  g_H1lo[33554432];
__device__ bf16  g_H2hi[33554432];   // hidden2 (post conv2+relu)
__device__ bf16  g_H2lo[33554432];
__device__ float g_H1  [ 4194304];   // duration-path fp32 hiddens
__device__ float g_H2  [ 4194304];
__device__ bf16  g_Wsp [4][589824];  // split weights [n=256, k'=2304] = [Whi|Wlo|Whi]
__device__ int   g_cs  [16384];      // cumsum durations

// ==================================================================
// helpers
// ==================================================================
__device__ __forceinline__ uint32_t smem_u32(const void* p) {
    uint32_t a;
    asm("{ .reg .u64 t; cvta.to.shared.u64 t, %1; cvt.u32.u64 %0, t; }" : "=r"(a) : "l"(p));
    return a;
}
#define SWZ(o) ((o) ^ (((o) >> 3) & 0x70))

__device__ __forceinline__ void cpa16(uint32_t dst, const void* src, int pred) {
    int sz = pred ? 16 : 0;
    asm volatile("cp.async.cg.shared.global [%0], [%1], 16, %2;" :: "r"(dst), "l"(src), "r"(sz));
}
__device__ __forceinline__ uint32_t pack2(float lo, float hi) {
    uint32_t r;
    asm("cvt.rn.bf16x2.f32 %0, %1, %2;" : "=r"(r) : "f"(hi), "f"(lo));
    return r;
}
__device__ __forceinline__ float bf16_round(float v) {
    return __bfloat162float(__float2bfloat16(v));
}
__device__ __forceinline__ void ldm4(uint32_t r[4], uint32_t addr) {
    asm volatile("ldmatrix.sync.aligned.m8n8.x4.shared.b16 {%0,%1,%2,%3}, [%4];"
        : "=r"(r[0]), "=r"(r[1]), "=r"(r[2]), "=r"(r[3]) : "r"(addr));
}
__device__ __forceinline__ void mma16816(float c[4], const uint32_t a[4],
                                         uint32_t b0, uint32_t b1) {
    asm volatile("mma.sync.aligned.m16n8k16.row.col.f32.bf16.bf16.f32 "
        "{%0,%1,%2,%3}, {%4,%5,%6,%7}, {%8,%9}, {%0,%1,%2,%3};"
        : "+f"(c[0]), "+f"(c[1]), "+f"(c[2]), "+f"(c[3])
        : "r"(a[0]), "r"(a[1]), "r"(a[2]), "r"(a[3]), "r"(b0), "r"(b1));
}

// ==================================================================
// split-bf16 HMMA conv(k=3, 256->256) GEMM
// C = Ahi*Whi + Ahi*Wlo + Alo*Whi  (virtual K' = 2304, chunks of 64)
// W layout: [n=256, 2304] = [Whi(768) | Wlo(768) | Whi(768)]
// out: relu(C + bias) written as hi/lo bf16 pair.
// Tile 128(M) x 128(N), double-buffered cp.async, SW128 swizzle.
// ==================================================================
#define HSTG 32768            // per-stage: A 16KB + B 16KB

__global__ __launch_bounds__(256, 2)
void hmma_conv_sp(const bf16* __restrict__ Ahi, const bf16* __restrict__ Alo,
                  const bf16* __restrict__ W, const float* __restrict__ bias,
                  bf16* __restrict__ outhi, bf16* __restrict__ outlo, int S)
{
    extern __shared__ char sm[];
    uint32_t smb = smem_u32(sm);
    int tid  = threadIdx.x;
    int lane = tid & 31;
    int wid  = tid >> 5;
    int warp_m = (wid & 3) * 32;     // 4 warps over M
    int warp_n = (wid >> 2) * 64;    // 2 warps over N

    int m0 = blockIdx.x * 128;
    int b  = m0 / S;
    int t0 = m0 - b * S;
    int n0 = blockIdx.y * 128;

    auto load_chunk = [&](int ci, int stg) {
        int part = ci / 12;               // 0: Ahi*Whi, 1: Ahi*Wlo, 2: Alo*Whi
        int cc   = ci - part * 12;
        int k0in = cc * 64;
        int tap = k0in >> 8, c0 = k0in & 255;
        const bf16* Ab = ((part == 2) ? Alo : Ahi) + (size_t)b * S * 256;
        int k0w = ci * 64;
        uint32_t Asm = smb + stg * HSTG;
        uint32_t Bsm = Asm + 16384;
        #pragma unroll
        for (int j = 0; j < 4; j++) {                 // A: 128 rows x 128B
            int u = tid + 256 * j, row = u >> 3, c16 = u & 7;
            int tr = t0 + row + tap - 1;
            cpa16(Asm + SWZ(row * 128 + c16 * 16),
                  Ab + (size_t)tr * 256 + c0 + c16 * 8,
                  (unsigned)tr < (unsigned)S);
        }
        #pragma unroll
        for (int j = 0; j < 4; j++) {                 // B: 128 n-rows x 128B
            int u = tid + 256 * j, n = u >> 3, c16 = u & 7;
            cpa16(Bsm + SWZ(n * 128 + c16 * 16),
                  W + (size_t)(n0 + n) * 2304 + k0w + c16 * 8, 1);
        }
    };

    float acc[2][8][4];
    #pragma unroll
    for (int i = 0; i < 2; i++)
        #pragma unroll
        for (int j = 0; j < 8; j++)
            #pragma unroll
            for (int e = 0; e < 4; e++) acc[i][j][e] = 0.f;

    int g = lane >> 3;
    int arow = ((g & 1) << 3) + (lane & 7);
    int akk  = (g >> 1) << 3;
    int brow = ((g >> 1) << 3) + (lane & 7);
    int bkk  = (g & 1) << 3;

    load_chunk(0, 0);
    asm volatile("cp.async.commit_group;" ::: "memory");

    const int NC = 36;                    // 2304 / 64
    for (int i = 0; i < NC; i++) {
        if (i + 1 < NC) {
            load_chunk(i + 1, (i + 1) & 1);
            asm volatile("cp.async.commit_group;" ::: "memory");
            asm volatile("cp.async.wait_group 1;" ::: "memory");
        } else {
            asm volatile("cp.async.wait_group 0;" ::: "memory");
        }
        __syncthreads();

        uint32_t Asm = smb + (i & 1) * HSTG;
        uint32_t Bsm = Asm + 16384;
        #pragma unroll
        for (int ks = 0; ks < 4; ks++) {
            int kk = ks * 16;
            uint32_t a[2][4], bq[4][4];
            #pragma unroll
            for (int mt = 0; mt < 2; mt++) {
                int row = warp_m + mt * 16 + arow;
                ldm4(a[mt], Asm + SWZ(row * 128 + (kk + akk) * 2));
            }
            #pragma unroll
            for (int q = 0; q < 4; q++) {
                int n = warp_n + q * 16 + brow;
                ldm4(bq[q], Bsm + SWZ(n * 128 + (kk + bkk) * 2));
            }
            #pragma unroll
            for (int mt = 0; mt < 2; mt++)
                #pragma unroll
                for (int nb = 0; nb < 8; nb++) {
                    int q = nb >> 1, h = (nb & 1) * 2;
                    mma16816(acc[mt][nb], a[mt], bq[q][h], bq[q][h + 1]);
                }
        }
        __syncthreads();
    }

    // epilogue: bias + relu -> hi/lo bf16
    int colq = (lane & 3) * 2;
    int rowq = lane >> 2;
    #pragma unroll
    for (int mt = 0; mt < 2; mt++) {
        #pragma unroll
        for (int nb = 0; nb < 8; nb++) {
            int col = n0 + warp_n + nb * 8 + colq;
            float bs0 = bias[col], bs1 = bias[col + 1];
            int tokA = m0 + warp_m + mt * 16 + rowq;
            int tokB = tokA + 8;
            float v0 = fmaxf(acc[mt][nb][0] + bs0, 0.f);
            float v1 = fmaxf(acc[mt][nb][1] + bs1, 0.f);
            float v2 = fmaxf(acc[mt][nb][2] + bs0, 0.f);
            float v3 = fmaxf(acc[mt][nb][3] + bs1, 0.f);
            float h0 = bf16_round(v0), h1 = bf16_round(v1);
            float h2 = bf16_round(v2), h3 = bf16_round(v3);
            *(uint32_t*)(outhi + (size_t)tokA * 256 + col) = pack2(h0, h1);
            *(uint32_t*)(outhi + (size_t)tokB * 256 + col) = pack2(h2, h3);
            *(uint32_t*)(outlo + (size_t)tokA * 256 + col) = pack2(v0 - h0, v1 - h1);
            *(uint32_t*)(outlo + (size_t)tokB * 256 + col) = pack2(v2 - h2, v3 - h3);
        }
    }
}

// ==================================================================
// weight repack with hi/lo split:
// src w[pred][kk][c][n] f32 -> g_Wsp[mat][n*2304 + blk*768 + kk*256 + c]
// blk 0 = Whi, blk 1 = Wlo, blk 2 = Whi.  mats: 0=(w1,p1) 1=(w2,p1) 2=(w1,p2) 3=(w2,p2)
// ==================================================================
__global__ void repack_w_sp(const float* __restrict__ w1, const float* __restrict__ w2)
{
    int e = blockIdx.x * 256 + threadIdx.x;      // 4 * 589824 total
    int mat = e / 589824;
    int r   = e - mat * 589824;
    int n = r / 2304, kq = r - n * 2304;
    int blk = kq / 768, k = kq - blk * 768;
    int kk = k >> 8, c = k & 255;
    int p = (mat >> 1) + 1;
    const float* src = (mat & 1) ? w2 : w1;
    float w = src[(((size_t)p * 3 + kk) * 256 + c) * 256 + n];
    float hi = __bfloat162float(__float2bfloat16(w));
    g_Wsp[mat][r] = __float2bfloat16(blk == 1 ? (w - hi) : w);
}

// ==================================================================
// LayerNorm on hi/lo pair (warp per token), fp32 stats, hi/lo out
// ==================================================================
__global__ void ln_pair_kernel(bf16* __restrict__ hi, bf16* __restrict__ lo,
                               const float* __restrict__ sc, const float* __restrict__ bi,
                               int ntok)
{
    int w = threadIdx.x >> 5, lane = threadIdx.x & 31;
    int t = blockIdx.x * 8 + w;
    if (t >= ntok) return;
    size_t base = (size_t)t * 256 + lane * 8;
    uint4 rh = *(uint4*)(hi + base);
    uint4 rl = *(uint4*)(lo + base);
    uint32_t ph[4] = {rh.x, rh.y, rh.z, rh.w};
    uint32_t pl[4] = {rl.x, rl.y, rl.z, rl.w};
    float v[8];
    #pragma unroll
    for (int j = 0; j < 4; j++) {
        v[2*j]   = __bfloat162float(((bf16*)&ph[j])[0]) + __bfloat162float(((bf16*)&pl[j])[0]);
        v[2*j+1] = __bfloat162float(((bf16*)&ph[j])[1]) + __bfloat162float(((bf16*)&pl[j])[1]);
    }
    float s = 0.f, q = 0.f;
    #pragma unroll
    for (int j = 0; j < 8; j++) { s += v[j]; q += v[j] * v[j]; }
    #pragma unroll
    for (int o = 16; o; o >>= 1) {
        s += __shfl_xor_sync(0xffffffffu, s, o);
        q += __shfl_xor_sync(0xffffffffu, q, o);
    }
    float m = s * (1.f / 256.f);
    float r = rsqrtf(q * (1.f / 256.f) - m * m + 1e-5f);
    float4 s0 = *(const float4*)(sc + lane * 8);
    float4 s1 = *(const float4*)(sc + lane * 8 + 4);
    float4 b0 = *(const float4*)(bi + lane * 8);
    float4 b1 = *(const float4*)(bi + lane * 8 + 4);
    float sa[8] = {s0.x, s0.y, s0.z, s0.w, s1.x, s1.y, s1.z, s1.w};
    float ba[8] = {b0.x, b0.y, b0.z, b0.w, b1.x, b1.y, b1.z, b1.w};
    uint32_t oh[4], ol[4];
    #pragma unroll
    for (int j = 0; j < 4; j++) {
        float o0 = (v[2*j]   - m) * r * sa[2*j]   + ba[2*j];
        float o1 = (v[2*j+1] - m) * r * sa[2*j+1] + ba[2*j+1];
        float h0 = bf16_round(o0), h1 = bf16_round(o1);
        oh[j] = pack2(h0, h1);
        ol[j] = pack2(o0 - h0, o1 - h1);
    }
    *(uint4*)(hi + base) = make_uint4(oh[0], oh[1], oh[2], oh[3]);
    *(uint4*)(lo + base) = make_uint4(ol[0], ol[1], ol[2], ol[3]);
}

// ==================================================================
// fused LN + linear F->1 + mask on hi/lo pair (warp per token)
// ==================================================================
__global__ void lnlin_pair_kernel(const bf16* __restrict__ hi, const bf16* __restrict__ lo,
                                  const float* __restrict__ sc, const float* __restrict__ bi,
                                  const float* __restrict__ lw, const float* __restrict__ lb,
                                  const unsigned char* __restrict__ mask,
                                  float* __restrict__ out, int ntok)
{
    int w = threadIdx.x >> 5, lane = threadIdx.x & 31;
    int t = blockIdx.x * 8 + w;
    if (t >= ntok) return;
    size_t base = (size_t)t * 256 + lane * 8;
    uint4 rh = *(const uint4*)(hi + base);
    uint4 rl = *(const uint4*)(lo + base);
    uint32_t ph[4] = {rh.x, rh.y, rh.z, rh.w};
    uint32_t pl[4] = {rl.x, rl.y, rl.z, rl.w};
    float v[8];
    #pragma unroll
    for (int j = 0; j < 4; j++) {
        v[2*j]   = __bfloat162float(((bf16*)&ph[j])[0]) + __bfloat162float(((bf16*)&pl[j])[0]);
        v[2*j+1] = __bfloat162float(((bf16*)&ph[j])[1]) + __bfloat162float(((bf16*)&pl[j])[1]);
    }
    float s = 0.f, q = 0.f;
    #pragma unroll
    for (int j = 0; j < 8; j++) { s += v[j]; q += v[j] * v[j]; }
    #pragma unroll
    for (int o = 16; o; o >>= 1) {
        s += __shfl_xor_sync(0xffffffffu, s, o);
        q += __shfl_xor_sync(0xffffffffu, q, o);
    }
    float m = s * (1.f / 256.f);
    float r = rsqrtf(q * (1.f / 256.f) - m * m + 1e-5f);
    float4 s0 = *(const float4*)(sc + lane * 8);
    float4 s1 = *(const float4*)(sc + lane * 8 + 4);
    float4 b0 = *(const float4*)(bi + lane * 8);
    float4 b1 = *(const float4*)(bi + lane * 8 + 4);
    float4 w0 = *(const float4*)(lw + lane * 8);
    float4 w1 = *(const float4*)(lw + lane * 8 + 4);
    float sa[8] = {s0.x, s0.y, s0.z, s0.w, s1.x, s1.y, s1.z, s1.w};
    float ba[8] = {b0.x, b0.y, b0.z, b0.w, b1.x, b1.y, b1.z, b1.w};
    float wa[8] = {w0.x, w0.y, w0.z, w0.w, w1.x, w1.y, w1.z, w1.w};
    float d = 0.f;
    #pragma unroll
    for (int j = 0; j < 8; j++)
        d += ((v[j] - m) * r * sa[j] + ba[j]) * wa[j];
    #pragma unroll
    for (int o = 16; o; o >>= 1) d += __shfl_xor_sync(0xffffffffu, d, o);
    if (lane == 0) {
        float val = d + lb[0];
        if (mask[t]) val = 0.f;
        out[t] = val;
    }
}

// ==================================================================
// fp32 duration-path GEMM (exact, proven R1 code)
// ==================================================================
#define BM 128
#define BN 128
#define BK 16
#define NKT 48

__device__ __forceinline__ void cg_load(const float* __restrict__ inb,
                                        const float* __restrict__ W,
                                        int S, int t0, int n0, int kt, int tid,
                                        float4 av[2], float4 bv[2]) {
    int kc = kt * BK;
    int kk = kc >> 8, c0 = kc & 255;
    #pragma unroll
    for (int it = 0; it < 2; it++) {
        int idx = tid + it * 256;
        int m = idx >> 2, v = idx & 3;
        int t = t0 + m + kk - 1;
        float4 a = make_float4(0.f, 0.f, 0.f, 0.f);
        if (t >= 0 && t < S)
            a = *(const float4*)(inb + (size_t)t * 256 + c0 + v * 4);
        av[it] = a;
        int k = idx >> 5, nv = idx & 31;
        bv[it] = *(const float4*)(W + (size_t)(kc + k) * 256 + n0 + nv * 4);
    }
}
__device__ __forceinline__ void cg_store(float* As, float* Bs, int tid,
                                         const float4 av[2], const float4 bv[2]) {
    #pragma unroll
    for (int it = 0; it < 2; it++) {
        int idx = tid + it * 256;
        int m = idx >> 2, v = idx & 3;
        float vals[4] = {av[it].x, av[it].y, av[it].z, av[it].w};
        #pragma unroll
        for (int w = 0; w < 4; w++)
            *(float2*)&As[(v * 4 + w) * 256 + 2 * m] = make_float2(vals[w], vals[w]);
        int k = idx >> 5, nv = idx & 31;
        *(float4*)&Bs[k * BN + nv * 4] = bv[it];
    }
}
union U64F2 { unsigned long long u; float2 f; };
__device__ __forceinline__ void cg_compute(const float* As, const float* Bs,
                                           int ty, int tx, unsigned long long acc[8][4]) {
    #pragma unroll
    for (int k = 0; k < BK; k++) {
        const float* ar = As + k * 256 + 16 * ty;
        ulonglong2 q0 = *(const ulonglong2*)(ar + 0);
        ulonglong2 q1 = *(const ulonglong2*)(ar + 4);
        ulonglong2 q2 = *(const ulonglong2*)(ar + 8);
        ulonglong2 q3 = *(const ulonglong2*)(ar + 12);
        unsigned long long a8[8] = {q0.x, q0.y, q1.x, q1.y, q2.x, q2.y, q3.x, q3.y};
        const float* br = Bs + k * BN + 8 * tx;
        ulonglong2 p0 = *(const ulonglong2*)(br + 0);
        ulonglong2 p1 = *(const ulonglong2*)(br + 4);
        unsigned long long b4[4] = {p0.x, p0.y, p1.x, p1.y};
        #pragma unroll
        for (int i = 0; i < 8; i++)
            #pragma unroll
            for (int j = 0; j < 4; j++)
                asm("fma.rn.f32x2 %0, %1, %2, %0;" : "+l"(acc[i][j]) : "l"(a8[i]), "l"(b4[j]));
    }
}
__global__ __launch_bounds__(256) void conv_gemm_kernel(
    const float* __restrict__ in, const float* __restrict__ W,
    const float* __restrict__ bias, float* __restrict__ out, int S)
{
    __shared__ float sm[12288];
    float* As0 = sm;        float* Bs0 = sm + 4096;
    float* As1 = sm + 6144; float* Bs1 = sm + 10240;
    int tid = threadIdx.x;
    int m0 = blockIdx.x * BM;
    int b  = m0 / S;
    int t0 = m0 - b * S;
    int n0 = blockIdx.y * BN;
    int ty = tid >> 4, tx = tid & 15;
    const float* inb = in + (size_t)b * S * 256;
    unsigned long long acc[8][4];
    #pragma unroll
    for (int i = 0; i < 8; i++)
        #pragma unroll
        for (int j = 0; j < 4; j++) acc[i][j] = 0ull;
    float4 av[2], bv[2];
    cg_load(inb, W, S, t0, n0, 0, tid, av, bv);
    cg_store(As0, Bs0, tid, av, bv);
    __syncthreads();
    for (int kt = 0; kt < NKT; kt++) {
        const float* Ac = (kt & 1) ? As1 : As0;
        const float* Bc = (kt & 1) ? Bs1 : Bs0;
        float* An = (kt & 1) ? As0 : As1;
        float* Bn = (kt & 1) ? Bs0 : Bs1;
        if (kt + 1 < NKT) cg_load(inb, W, S, t0, n0, kt + 1, tid, av, bv);
        cg_compute(Ac, Bc, ty, tx, acc);
        if (kt + 1 < NKT) cg_store(An, Bn, tid, av, bv);
        __syncthreads();
    }
    const float* bp = bias + n0 + 8 * tx;
    float bs8[8];
    #pragma unroll
    for (int j = 0; j < 8; j++) bs8[j] = bp[j];
    #pragma unroll
    for (int i = 0; i < 8; i++) {
        int t = t0 + 8 * ty + i;
        float* orow = out + ((size_t)b * S + t) * 256 + n0 + 8 * tx;
        float o[8];
        #pragma unroll
        for (int j = 0; j < 4; j++) { U64F2 c; c.u = acc[i][j]; o[2*j] = c.f.x; o[2*j+1] = c.f.y; }
        #pragma unroll
        for (int j = 0; j < 8; j++) o[j] = fmaxf(o[j] + bs8[j], 0.f);
        *(float4*)(orow)     = make_float4(o[0], o[1], o[2], o[3]);
        *(float4*)(orow + 4) = make_float4(o[4], o[5], o[6], o[7]);
    }
}

__global__ void ln_kernel(float* __restrict__ h, const float* __restrict__ sc,
                          const float* __restrict__ bi, int ntok)
{
    int w = threadIdx.x >> 5, lane = threadIdx.x & 31;
    int t = blockIdx.x * 8 + w;
    if (t >= ntok) return;
    float* row = h + (size_t)t * 256;
    float4 v0 = *(float4*)(row + lane * 4);
    float4 v1 = *(float4*)(row + 128 + lane * 4);
    float s = v0.x + v0.y + v0.z + v0.w + v1.x + v1.y + v1.z + v1.w;
    float q = v0.x*v0.x + v0.y*v0.y + v0.z*v0.z + v0.w*v0.w
            + v1.x*v1.x + v1.y*v1.y + v1.z*v1.z + v1.w*v1.w;
    #pragma unroll
    for (int o = 16; o; o >>= 1) {
        s += __shfl_xor_sync(0xffffffffu, s, o);
        q += __shfl_xor_sync(0xffffffffu, q, o);
    }
    float m = s * (1.f / 256.f);
    float r = rsqrtf(q * (1.f / 256.f) - m * m + 1e-5f);
    int f0 = lane * 4, f1 = 128 + lane * 4;
    float4 s0 = *(const float4*)(sc + f0), s1 = *(const float4*)(sc + f1);
    float4 b0 = *(const float4*)(bi + f0), b1 = *(const float4*)(bi + f1);
    v0.x = (v0.x - m)*r*s0.x + b0.x;  v0.y = (v0.y - m)*r*s0.y + b0.y;
    v0.z = (v0.z - m)*r*s0.z + b0.z;  v0.w = (v0.w - m)*r*s0.w + b0.w;
    v1.x = (v1.x - m)*r*s1.x + b1.x;  v1.y = (v1.y - m)*r*s1.y + b1.y;
    v1.z = (v1.z - m)*r*s1.z + b1.z;  v1.w = (v1.w - m)*r*s1.w + b1.w;
    *(float4*)(row + lane * 4)       = v0;
    *(float4*)(row + 128 + lane * 4) = v1;
}

__global__ void dur_final_kernel(const float* __restrict__ h, const float* __restrict__ lw,
                                 const float* __restrict__ lb,
                                 const unsigned char* __restrict__ mask,
                                 const int* __restrict__ scale,
                                 float* __restrict__ out, int ntok)
{
    int w = threadIdx.x >> 5, lane = threadIdx.x & 31;
    int t = blockIdx.x * 8 + w;
    if (t >= ntok) return;
    const float* row = h + (size_t)t * 256;
    float4 v0 = *(const float4*)(row + lane * 4);
    float4 v1 = *(const float4*)(row + 128 + lane * 4);
    float4 w0 = *(const float4*)(lw + lane * 4);
    float4 w1 = *(const float4*)(lw + 128 + lane * 4);
    float d = v0.x*w0.x + v0.y*w0.y + v0.z*w0.z + v0.w*w0.w
            + v1.x*w1.x + v1.y*w1.y + v1.z*w1.z + v1.w*w1.w;
    #pragma unroll
    for (int o = 16; o; o >>= 1) d += __shfl_xor_sync(0xffffffffu, d, o);
    if (lane == 0) {
        float val = d + lb[0];
        if (mask[t]) val = 0.f;
        out[t] = fmaxf(rintf(expf(val) * (float)(*scale)), 0.f);
    }
}

// ==================================================================
// cumsum / length-regulate / embedding add
// ==================================================================
__global__ void cumsum_kernel(const int* __restrict__ dur, int* __restrict__ cs)
{
    __shared__ int s[512];
    int b = blockIdx.x, t = threadIdx.x;
    s[t] = dur[b * 512 + t];
    __syncthreads();
    for (int off = 1; off < 512; off <<= 1) {
        int v = (t >= off) ? s[t - off] : 0;
        __syncthreads();
        s[t] += v;
        __syncthreads();
    }
    cs[b * 512 + t] = s[t];
}

__global__ void length_reg_kernel(const float* __restrict__ hidden,
                                  const int* __restrict__ cs,
                                  float* __restrict__ X,
                                  bf16* __restrict__ Xhi, bf16* __restrict__ Xlo)
{
    __shared__ int scs[512];
    int tid = threadIdx.x;
    int base = blockIdx.x * 4;
    int b    = base >> 12;
    int tloc = base & 4095;
    const int* csb = cs + b * 512;
    scs[tid] = csb[tid];
    scs[tid + 256] = csb[tid + 256];
    __syncthreads();
    int g = tid >> 6, lane = tid & 63;
    int t = tloc + g;
    int lo = 0, hi = 512;
    while (lo < hi) { int mid = (lo + hi) >> 1; if (scs[mid] <= t) lo = mid + 1; else hi = mid; }
    int idx = lo < 512 ? lo : 511;
    bool valid = t < scs[511];
    float4 v = make_float4(0.f, 0.f, 0.f, 0.f);
    if (valid) v = *(const float4*)(hidden + ((size_t)b * 512 + idx) * 256 + lane * 4);
    size_t off = ((size_t)b * 4096 + t) * 256 + lane * 4;
    *(float4*)(X + off) = v;
    float hx = bf16_round(v.x), hy = bf16_round(v.y);
    float hz = bf16_round(v.z), hw = bf16_round(v.w);
    *(uint2*)(Xhi + off) = make_uint2(pack2(hx, hy), pack2(hz, hw));
    *(uint2*)(Xlo + off) = make_uint2(pack2(v.x - hx, v.y - hy), pack2(v.z - hz, v.w - hw));
}

__global__ void add_emb_kernel(const float* __restrict__ X, const float* __restrict__ tgt,
                               const float* __restrict__ bins, const float* __restrict__ emb,
                               float* __restrict__ outp,
                               bf16* __restrict__ Xhi, bf16* __restrict__ Xlo, int wxb)
{
    __shared__ float sb[256];
    int tid = threadIdx.x;
    sb[tid] = bins[tid];
    __syncthreads();
    int base = blockIdx.x * 4;
    int g = tid >> 6, lane = tid & 63;
    int t = base + g;
    float v = tgt[t];
    int lo = 0, hi = 256;
    while (lo < hi) { int mid = (lo + hi) >> 1; if (sb[mid] < v) lo = mid + 1; else hi = mid; }
    int idx = lo < 256 ? lo : 255;
    size_t off = (size_t)t * 256 + lane * 4;
    float4 a = *(const float4*)(X + off);
    float4 e = *(const float4*)(emb + (size_t)idx * 256 + lane * 4);
    a.x += e.x; a.y += e.y; a.z += e.z; a.w += e.w;
    *(float4*)(outp + off) = a;
    if (wxb) {
        float hx = bf16_round(a.x), hy = bf16_round(a.y);
        float hz = bf16_round(a.z), hw = bf16_round(a.w);
        *(uint2*)(Xhi + off) = make_uint2(pack2(hx, hy), pack2(hz, hw));
        *(uint2*)(Xlo + off) = make_uint2(pack2(a.x - hx, a.y - hy), pack2(a.z - hz, a.w - hw));
    }
}

// ==================================================================
// launch
// ==================================================================
extern "C" void kernel_launch(void* const* d_in, const int* in_sizes, int n_in,
                              void* d_out, int out_size)
{
    const float*         hidden    = (const float*)d_in[0];
    const unsigned char* mask      = (const unsigned char*)d_in[1];
    const unsigned char* fmask     = (const unsigned char*)d_in[2];
    const int*           dur_tgt   = (const int*)d_in[3];
    const float*         pitch_tgt = (const float*)d_in[4];
    const float*         energy_tgt= (const float*)d_in[5];
    const int*           dscale    = (const int*)d_in[6];
    const float*         w1        = (const float*)d_in[7];
    const float*         b1        = (const float*)d_in[8];
    const float*         l1s       = (const float*)d_in[9];
    const float*         l1b       = (const float*)d_in[10];
    const float*         w2        = (const float*)d_in[11];
    const float*         b2        = (const float*)d_in[12];
    const float*         l2s       = (const float*)d_in[13];
    const float*         l2b       = (const float*)d_in[14];
    const float*         lw        = (const float*)d_in[15];
    const float*         lb        = (const float*)d_in[16];
    const float*         pbins     = (const float*)d_in[17];
    const float*         pemb      = (const float*)d_in[18];
    const float*         ebins     = (const float*)d_in[19];
    const float*         eemb      = (const float*)d_in[20];

    cudaFuncSetAttribute(hmma_conv_sp, cudaFuncAttributeMaxDynamicSharedMemorySize, 2 * HSTG);

    float* X;  bf16 *Xhi, *Xlo, *H1hi, *H1lo, *H2hi, *H2lo, *Wsp;
    float *H1, *H2;  int* cs;
    cudaGetSymbolAddress((void**)&X,    g_X);
    cudaGetSymbolAddress((void**)&Xhi,  g_Xhi);
    cudaGetSymbolAddress((void**)&Xlo,  g_Xlo);
    cudaGetSymbolAddress((void**)&H1hi, g_H1hi);
    cudaGetSymbolAddress((void**)&H1lo, g_H1lo);
    cudaGetSymbolAddress((void**)&H2hi, g_H2hi);
    cudaGetSymbolAddress((void**)&H2lo, g_H2lo);
    cudaGetSymbolAddress((void**)&H1,   g_H1);
    cudaGetSymbolAddress((void**)&H2,   g_H2);
    cudaGetSymbolAddress((void**)&cs,   g_cs);
    cudaGetSymbolAddress((void**)&Wsp,  g_Wsp);

    float* out_rd     = (float*)d_out;
    float* out_pitch  = out_rd + 32 * 512;
    float* out_energy = out_pitch + 32 * 4096;
    float* out_ve     = out_energy + 32 * 4096;

    repack_w_sp<<<9216, 256>>>(w1, w2);

    // ---- duration predictor (fp32 exact; S=512, 16384 tokens) ----
    {
        dim3 g(16384 / 128, 2);
        conv_gemm_kernel<<<g, 256>>>(hidden, w1, b1, H1, 512);
        ln_kernel<<<16384 / 8, 256>>>(H1, l1s, l1b, 16384);
        conv_gemm_kernel<<<g, 256>>>(H1, w2, b2, H2, 512);
        ln_kernel<<<16384 / 8, 256>>>(H2, l2s, l2b, 16384);
        dur_final_kernel<<<16384 / 8, 256>>>(H2, lw, lb, mask, dscale, out_rd, 16384);
    }

    // ---- length regulate ----
    cumsum_kernel<<<32, 512>>>(dur_tgt, cs);
    length_reg_kernel<<<32 * 4096 / 4, 256>>>(hidden, cs, X, Xhi, Xlo);

    const int NT = 131072;
    dim3 gg(NT / 128, 2);

    // ---- pitch predictor (split-bf16 HMMA) ----
    hmma_conv_sp<<<gg, 256, 2 * HSTG>>>(Xhi,  Xlo,  Wsp + 0 * 589824, b1 + 256, H1hi, H1lo, 4096);
    ln_pair_kernel<<<NT / 8, 256>>>(H1hi, H1lo, l1s + 256, l1b + 256, NT);
    hmma_conv_sp<<<gg, 256, 2 * HSTG>>>(H1hi, H1lo, Wsp + 1 * 589824, b2 + 256, H2hi, H2lo, 4096);
    lnlin_pair_kernel<<<NT / 8, 256>>>(H2hi, H2lo, l2s + 256, l2b + 256,
                                       lw + 256, lb + 1, fmask, out_pitch, NT);
    add_emb_kernel<<<NT / 4, 256>>>(X, pitch_tgt, pbins, pemb, X, Xhi, Xlo, 1);

    // ---- energy predictor (split-bf16 HMMA) ----
    hmma_conv_sp<<<gg, 256, 2 * HSTG>>>(Xhi,  Xlo,  Wsp + 2 * 589824, b1 + 512, H1hi, H1lo, 4096);
    ln_pair_kernel<<<NT / 8, 256>>>(H1hi, H1lo, l1s + 512, l1b + 512, NT);
    hmma_conv_sp<<<gg, 256, 2 * HSTG>>>(H1hi, H1lo, Wsp + 3 * 589824, b2 + 512, H2hi, H2lo, 4096);
    lnlin_pair_kernel<<<NT / 8, 256>>>(H2hi, H2lo, l2s + 512, l2b + 512,
                                       lw + 512, lb + 2, fmask, out_energy, NT);
    add_emb_kernel<<<NT / 4, 256>>>(X, energy_tgt, ebins, eemb, out_ve, nullptr, nullptr, 0);
}

// round 7
// speedup vs baseline: 2.8963x; 1.5268x over previous
#include <cuda_runtime.h>
#include <cuda_bf16.h>
#include <math.h>
#include <stdint.h>

typedef __nv_bfloat16 bf16;

// B=32, L=512, T=4096, E=F=256, NB=256
// Output: concat(rounded_duration[B*L], pitch[B*T], energy[B*T], variance_embedding[B*T*E])

// -------- scratch (device globals) --------
__device__ float g_X   [33554432];   // [B,T,E] fp32 length-regulated x (exact path)
__device__ bf16  g_Xhi [33554432];   // hi/lo bf16 split of X
__device__ bf16  g_Xlo [33554432];
__device__ bf16  g_H1hi[33554432];   // hidden1 (post conv1+relu, then LN in-place)
__device__ bf16  g_H1lo[33554432];
__device__ bf16  g_H2hi[33554432];   // hidden2 (post conv2+relu)
__device__ bf16  g_H2lo[33554432];
__device__ float g_H1  [ 4194304];   // duration-path fp32 hiddens
__device__ float g_H2  [ 4194304];
__device__ bf16  g_Wsp [4][589824];  // split weights [n=256, k'=2304] = [Whi|Wlo|Whi]
__device__ int   g_cs  [16384];      // cumsum durations

// ==================================================================
// helpers
// ==================================================================
__device__ __forceinline__ uint32_t smem_u32(const void* p) {
    uint32_t a;
    asm("{ .reg .u64 t; cvta.to.shared.u64 t, %1; cvt.u32.u64 %0, t; }" : "=r"(a) : "l"(p));
    return a;
}
#define SWZ(o) ((o) ^ (((o) >> 3) & 0x70))

__device__ __forceinline__ void cpa16(uint32_t dst, const void* src, int pred) {
    int sz = pred ? 16 : 0;
    asm volatile("cp.async.cg.shared.global [%0], [%1], 16, %2;" :: "r"(dst), "l"(src), "r"(sz));
}
__device__ __forceinline__ uint32_t pack2(float lo, float hi) {
    uint32_t r;
    asm("cvt.rn.bf16x2.f32 %0, %1, %2;" : "=r"(r) : "f"(hi), "f"(lo));
    return r;
}
__device__ __forceinline__ float bf16_round(float v) {
    return __bfloat162float(__float2bfloat16(v));
}
__device__ __forceinline__ void ldm4(uint32_t r[4], uint32_t addr) {
    asm volatile("ldmatrix.sync.aligned.m8n8.x4.shared.b16 {%0,%1,%2,%3}, [%4];"
        : "=r"(r[0]), "=r"(r[1]), "=r"(r[2]), "=r"(r[3]) : "r"(addr));
}
__device__ __forceinline__ void mma16816(float c[4], const uint32_t a[4],
                                         uint32_t b0, uint32_t b1) {
    asm volatile("mma.sync.aligned.m16n8k16.row.col.f32.bf16.bf16.f32 "
        "{%0,%1,%2,%3}, {%4,%5,%6,%7}, {%8,%9}, {%0,%1,%2,%3};"
        : "+f"(c[0]), "+f"(c[1]), "+f"(c[2]), "+f"(c[3])
        : "r"(a[0]), "r"(a[1]), "r"(a[2]), "r"(a[3]), "r"(b0), "r"(b1));
}

// ==================================================================
// split-bf16 HMMA conv(k=3, 256->256) GEMM
// C = Ahi*Whi + Ahi*Wlo + Alo*Whi  (virtual K' = 2304, chunks of 64)
// W layout: [n=256, 2304] = [Whi(768) | Wlo(768) | Whi(768)]
// out: relu(C + bias) written as hi/lo bf16 pair.
// Tile 128(M) x 128(N), double-buffered cp.async, SW128 swizzle.
// ==================================================================
#define HSTG 32768            // per-stage: A 16KB + B 16KB

__global__ __launch_bounds__(256, 2)
void hmma_conv_sp(const bf16* __restrict__ Ahi, const bf16* __restrict__ Alo,
                  const bf16* __restrict__ W, const float* __restrict__ bias,
                  bf16* __restrict__ outhi, bf16* __restrict__ outlo, int S)
{
    extern __shared__ char sm[];
    uint32_t smb = smem_u32(sm);
    int tid  = threadIdx.x;
    int lane = tid & 31;
    int wid  = tid >> 5;
    int warp_m = (wid & 3) * 32;     // 4 warps over M
    int warp_n = (wid >> 2) * 64;    // 2 warps over N

    int m0 = blockIdx.x * 128;
    int b  = m0 / S;
    int t0 = m0 - b * S;
    int n0 = blockIdx.y * 128;

    auto load_chunk = [&](int ci, int stg) {
        int part = ci / 12;               // 0: Ahi*Whi, 1: Ahi*Wlo, 2: Alo*Whi
        int cc   = ci - part * 12;
        int k0in = cc * 64;
        int tap = k0in >> 8, c0 = k0in & 255;
        const bf16* Ab = ((part == 2) ? Alo : Ahi) + (size_t)b * S * 256;
        int k0w = ci * 64;
        uint32_t Asm = smb + stg * HSTG;
        uint32_t Bsm = Asm + 16384;
        #pragma unroll
        for (int j = 0; j < 4; j++) {                 // A: 128 rows x 128B
            int u = tid + 256 * j, row = u >> 3, c16 = u & 7;
            int tr = t0 + row + tap - 1;
            cpa16(Asm + SWZ(row * 128 + c16 * 16),
                  Ab + (size_t)tr * 256 + c0 + c16 * 8,
                  (unsigned)tr < (unsigned)S);
        }
        #pragma unroll
        for (int j = 0; j < 4; j++) {                 // B: 128 n-rows x 128B
            int u = tid + 256 * j, n = u >> 3, c16 = u & 7;
            cpa16(Bsm + SWZ(n * 128 + c16 * 16),
                  W + (size_t)(n0 + n) * 2304 + k0w + c16 * 8, 1);
        }
    };

    float acc[2][8][4];
    #pragma unroll
    for (int i = 0; i < 2; i++)
        #pragma unroll
        for (int j = 0; j < 8; j++)
            #pragma unroll
            for (int e = 0; e < 4; e++) acc[i][j][e] = 0.f;

    int g = lane >> 3;
    int arow = ((g & 1) << 3) + (lane & 7);
    int akk  = (g >> 1) << 3;
    int brow = ((g >> 1) << 3) + (lane & 7);
    int bkk  = (g & 1) << 3;

    load_chunk(0, 0);
    asm volatile("cp.async.commit_group;" ::: "memory");

    const int NC = 36;                    // 2304 / 64
    for (int i = 0; i < NC; i++) {
        if (i + 1 < NC) {
            load_chunk(i + 1, (i + 1) & 1);
            asm volatile("cp.async.commit_group;" ::: "memory");
            asm volatile("cp.async.wait_group 1;" ::: "memory");
        } else {
            asm volatile("cp.async.wait_group 0;" ::: "memory");
        }
        __syncthreads();

        uint32_t Asm = smb + (i & 1) * HSTG;
        uint32_t Bsm = Asm + 16384;
        #pragma unroll
        for (int ks = 0; ks < 4; ks++) {
            int kk = ks * 16;
            uint32_t a[2][4], bq[4][4];
            #pragma unroll
            for (int mt = 0; mt < 2; mt++) {
                int row = warp_m + mt * 16 + arow;
                ldm4(a[mt], Asm + SWZ(row * 128 + (kk + akk) * 2));
            }
            #pragma unroll
            for (int q = 0; q < 4; q++) {
                int n = warp_n + q * 16 + brow;
                ldm4(bq[q], Bsm + SWZ(n * 128 + (kk + bkk) * 2));
            }
            #pragma unroll
            for (int mt = 0; mt < 2; mt++)
                #pragma unroll
                for (int nb = 0; nb < 8; nb++) {
                    int q = nb >> 1, h = (nb & 1) * 2;
                    mma16816(acc[mt][nb], a[mt], bq[q][h], bq[q][h + 1]);
                }
        }
        __syncthreads();
    }

    // epilogue: bias + relu -> hi/lo bf16
    int colq = (lane & 3) * 2;
    int rowq = lane >> 2;
    #pragma unroll
    for (int mt = 0; mt < 2; mt++) {
        #pragma unroll
        for (int nb = 0; nb < 8; nb++) {
            int col = n0 + warp_n + nb * 8 + colq;
            float bs0 = bias[col], bs1 = bias[col + 1];
            int tokA = m0 + warp_m + mt * 16 + rowq;
            int tokB = tokA + 8;
            float v0 = fmaxf(acc[mt][nb][0] + bs0, 0.f);
            float v1 = fmaxf(acc[mt][nb][1] + bs1, 0.f);
            float v2 = fmaxf(acc[mt][nb][2] + bs0, 0.f);
            float v3 = fmaxf(acc[mt][nb][3] + bs1, 0.f);
            float h0 = bf16_round(v0), h1 = bf16_round(v1);
            float h2 = bf16_round(v2), h3 = bf16_round(v3);
            *(uint32_t*)(outhi + (size_t)tokA * 256 + col) = pack2(h0, h1);
            *(uint32_t*)(outhi + (size_t)tokB * 256 + col) = pack2(h2, h3);
            *(uint32_t*)(outlo + (size_t)tokA * 256 + col) = pack2(v0 - h0, v1 - h1);
            *(uint32_t*)(outlo + (size_t)tokB * 256 + col) = pack2(v2 - h2, v3 - h3);
        }
    }
}

// ==================================================================
// weight repack with hi/lo split:
// src w[pred][kk][c][n] f32 -> g_Wsp[mat][n*2304 + blk*768 + kk*256 + c]
// blk 0 = Whi, blk 1 = Wlo, blk 2 = Whi.  mats: 0=(w1,p1) 1=(w2,p1) 2=(w1,p2) 3=(w2,p2)
// ==================================================================
__global__ void repack_w_sp(const float* __restrict__ w1, const float* __restrict__ w2)
{
    int e = blockIdx.x * 256 + threadIdx.x;      // 4 * 589824 total
    int mat = e / 589824;
    int r   = e - mat * 589824;
    int n = r / 2304, kq = r - n * 2304;
    int blk = kq / 768, k = kq - blk * 768;
    int kk = k >> 8, c = k & 255;
    int p = (mat >> 1) + 1;
    const float* src = (mat & 1) ? w2 : w1;
    float w = src[(((size_t)p * 3 + kk) * 256 + c) * 256 + n];
    float hi = __bfloat162float(__float2bfloat16(w));
    g_Wsp[mat][r] = __float2bfloat16(blk == 1 ? (w - hi) : w);
}

// ==================================================================
// LayerNorm on hi/lo pair (warp per token), fp32 stats, hi/lo out
// ==================================================================
__global__ void ln_pair_kernel(bf16* __restrict__ hi, bf16* __restrict__ lo,
                               const float* __restrict__ sc, const float* __restrict__ bi,
                               int ntok)
{
    int w = threadIdx.x >> 5, lane = threadIdx.x & 31;
    int t = blockIdx.x * 8 + w;
    if (t >= ntok) return;
    size_t base = (size_t)t * 256 + lane * 8;
    uint4 rh = *(uint4*)(hi + base);
    uint4 rl = *(uint4*)(lo + base);
    uint32_t ph[4] = {rh.x, rh.y, rh.z, rh.w};
    uint32_t pl[4] = {rl.x, rl.y, rl.z, rl.w};
    float v[8];
    #pragma unroll
    for (int j = 0; j < 4; j++) {
        v[2*j]   = __bfloat162float(((bf16*)&ph[j])[0]) + __bfloat162float(((bf16*)&pl[j])[0]);
        v[2*j+1] = __bfloat162float(((bf16*)&ph[j])[1]) + __bfloat162float(((bf16*)&pl[j])[1]);
    }
    float s = 0.f, q = 0.f;
    #pragma unroll
    for (int j = 0; j < 8; j++) { s += v[j]; q += v[j] * v[j]; }
    #pragma unroll
    for (int o = 16; o; o >>= 1) {
        s += __shfl_xor_sync(0xffffffffu, s, o);
        q += __shfl_xor_sync(0xffffffffu, q, o);
    }
    float m = s * (1.f / 256.f);
    float r = rsqrtf(q * (1.f / 256.f) - m * m + 1e-5f);
    float4 s0 = *(const float4*)(sc + lane * 8);
    float4 s1 = *(const float4*)(sc + lane * 8 + 4);
    float4 b0 = *(const float4*)(bi + lane * 8);
    float4 b1 = *(const float4*)(bi + lane * 8 + 4);
    float sa[8] = {s0.x, s0.y, s0.z, s0.w, s1.x, s1.y, s1.z, s1.w};
    float ba[8] = {b0.x, b0.y, b0.z, b0.w, b1.x, b1.y, b1.z, b1.w};
    uint32_t oh[4], ol[4];
    #pragma unroll
    for (int j = 0; j < 4; j++) {
        float o0 = (v[2*j]   - m) * r * sa[2*j]   + ba[2*j];
        float o1 = (v[2*j+1] - m) * r * sa[2*j+1] + ba[2*j+1];
        float h0 = bf16_round(o0), h1 = bf16_round(o1);
        oh[j] = pack2(h0, h1);
        ol[j] = pack2(o0 - h0, o1 - h1);
    }
    *(uint4*)(hi + base) = make_uint4(oh[0], oh[1], oh[2], oh[3]);
    *(uint4*)(lo + base) = make_uint4(ol[0], ol[1], ol[2], ol[3]);
}

// ==================================================================
// fused LN + linear F->1 + mask on hi/lo pair (warp per token)
// ==================================================================
__global__ void lnlin_pair_kernel(const bf16* __restrict__ hi, const bf16* __restrict__ lo,
                                  const float* __restrict__ sc, const float* __restrict__ bi,
                                  const float* __restrict__ lw, const float* __restrict__ lb,
                                  const unsigned char* __restrict__ mask,
                                  float* __restrict__ out, int ntok)
{
    int w = threadIdx.x >> 5, lane = threadIdx.x & 31;
    int t = blockIdx.x * 8 + w;
    if (t >= ntok) return;
    size_t base = (size_t)t * 256 + lane * 8;
    uint4 rh = *(const uint4*)(hi + base);
    uint4 rl = *(const uint4*)(lo + base);
    uint32_t ph[4] = {rh.x, rh.y, rh.z, rh.w};
    uint32_t pl[4] = {rl.x, rl.y, rl.z, rl.w};
    float v[8];
    #pragma unroll
    for (int j = 0; j < 4; j++) {
        v[2*j]   = __bfloat162float(((bf16*)&ph[j])[0]) + __bfloat162float(((bf16*)&pl[j])[0]);
        v[2*j+1] = __bfloat162float(((bf16*)&ph[j])[1]) + __bfloat162float(((bf16*)&pl[j])[1]);
    }
    float s = 0.f, q = 0.f;
    #pragma unroll
    for (int j = 0; j < 8; j++) { s += v[j]; q += v[j] * v[j]; }
    #pragma unroll
    for (int o = 16; o; o >>= 1) {
        s += __shfl_xor_sync(0xffffffffu, s, o);
        q += __shfl_xor_sync(0xffffffffu, q, o);
    }
    float m = s * (1.f / 256.f);
    float r = rsqrtf(q * (1.f / 256.f) - m * m + 1e-5f);
    float4 s0 = *(const float4*)(sc + lane * 8);
    float4 s1 = *(const float4*)(sc + lane * 8 + 4);
    float4 b0 = *(const float4*)(bi + lane * 8);
    float4 b1 = *(const float4*)(bi + lane * 8 + 4);
    float4 w0 = *(const float4*)(lw + lane * 8);
    float4 w1 = *(const float4*)(lw + lane * 8 + 4);
    float sa[8] = {s0.x, s0.y, s0.z, s0.w, s1.x, s1.y, s1.z, s1.w};
    float ba[8] = {b0.x, b0.y, b0.z, b0.w, b1.x, b1.y, b1.z, b1.w};
    float wa[8] = {w0.x, w0.y, w0.z, w0.w, w1.x, w1.y, w1.z, w1.w};
    float d = 0.f;
    #pragma unroll
    for (int j = 0; j < 8; j++)
        d += ((v[j] - m) * r * sa[j] + ba[j]) * wa[j];
    #pragma unroll
    for (int o = 16; o; o >>= 1) d += __shfl_xor_sync(0xffffffffu, d, o);
    if (lane == 0) {
        float val = d + lb[0];
        if (mask[t]) val = 0.f;
        out[t] = val;
    }
}

// ==================================================================
// fp32 duration-path GEMM (exact, proven R1 code)
// ==================================================================
#define BM 128
#define BN 128
#define BK 16
#define NKT 48

__device__ __forceinline__ void cg_load(const float* __restrict__ inb,
                                        const float* __restrict__ W,
                                        int S, int t0, int n0, int kt, int tid,
                                        float4 av[2], float4 bv[2]) {
    int kc = kt * BK;
    int kk = kc >> 8, c0 = kc & 255;
    #pragma unroll
    for (int it = 0; it < 2; it++) {
        int idx = tid + it * 256;
        int m = idx >> 2, v = idx & 3;
        int t = t0 + m + kk - 1;
        float4 a = make_float4(0.f, 0.f, 0.f, 0.f);
        if (t >= 0 && t < S)
            a = *(const float4*)(inb + (size_t)t * 256 + c0 + v * 4);
        av[it] = a;
        int k = idx >> 5, nv = idx & 31;
        bv[it] = *(const float4*)(W + (size_t)(kc + k) * 256 + n0 + nv * 4);
    }
}
__device__ __forceinline__ void cg_store(float* As, float* Bs, int tid,
                                         const float4 av[2], const float4 bv[2]) {
    #pragma unroll
    for (int it = 0; it < 2; it++) {
        int idx = tid + it * 256;
        int m = idx >> 2, v = idx & 3;
        float vals[4] = {av[it].x, av[it].y, av[it].z, av[it].w};
        #pragma unroll
        for (int w = 0; w < 4; w++)
            *(float2*)&As[(v * 4 + w) * 256 + 2 * m] = make_float2(vals[w], vals[w]);
        int k = idx >> 5, nv = idx & 31;
        *(float4*)&Bs[k * BN + nv * 4] = bv[it];
    }
}
union U64F2 { unsigned long long u; float2 f; };
__device__ __forceinline__ void cg_compute(const float* As, const float* Bs,
                                           int ty, int tx, unsigned long long acc[8][4]) {
    #pragma unroll
    for (int k = 0; k < BK; k++) {
        const float* ar = As + k * 256 + 16 * ty;
        ulonglong2 q0 = *(const ulonglong2*)(ar + 0);
        ulonglong2 q1 = *(const ulonglong2*)(ar + 4);
        ulonglong2 q2 = *(const ulonglong2*)(ar + 8);
        ulonglong2 q3 = *(const ulonglong2*)(ar + 12);
        unsigned long long a8[8] = {q0.x, q0.y, q1.x, q1.y, q2.x, q2.y, q3.x, q3.y};
        const float* br = Bs + k * BN + 8 * tx;
        ulonglong2 p0 = *(const ulonglong2*)(br + 0);
        ulonglong2 p1 = *(const ulonglong2*)(br + 4);
        unsigned long long b4[4] = {p0.x, p0.y, p1.x, p1.y};
        #pragma unroll
        for (int i = 0; i < 8; i++)
            #pragma unroll
            for (int j = 0; j < 4; j++)
                asm("fma.rn.f32x2 %0, %1, %2, %0;" : "+l"(acc[i][j]) : "l"(a8[i]), "l"(b4[j]));
    }
}
__global__ __launch_bounds__(256) void conv_gemm_kernel(
    const float* __restrict__ in, const float* __restrict__ W,
    const float* __restrict__ bias, float* __restrict__ out, int S)
{
    __shared__ float sm[12288];
    float* As0 = sm;        float* Bs0 = sm + 4096;
    float* As1 = sm + 6144; float* Bs1 = sm + 10240;
    int tid = threadIdx.x;
    int m0 = blockIdx.x * BM;
    int b  = m0 / S;
    int t0 = m0 - b * S;
    int n0 = blockIdx.y * BN;
    int ty = tid >> 4, tx = tid & 15;
    const float* inb = in + (size_t)b * S * 256;
    unsigned long long acc[8][4];
    #pragma unroll
    for (int i = 0; i < 8; i++)
        #pragma unroll
        for (int j = 0; j < 4; j++) acc[i][j] = 0ull;
    float4 av[2], bv[2];
    cg_load(inb, W, S, t0, n0, 0, tid, av, bv);
    cg_store(As0, Bs0, tid, av, bv);
    __syncthreads();
    for (int kt = 0; kt < NKT; kt++) {
        const float* Ac = (kt & 1) ? As1 : As0;
        const float* Bc = (kt & 1) ? Bs1 : Bs0;
        float* An = (kt & 1) ? As0 : As1;
        float* Bn = (kt & 1) ? Bs0 : Bs1;
        if (kt + 1 < NKT) cg_load(inb, W, S, t0, n0, kt + 1, tid, av, bv);
        cg_compute(Ac, Bc, ty, tx, acc);
        if (kt + 1 < NKT) cg_store(An, Bn, tid, av, bv);
        __syncthreads();
    }
    const float* bp = bias + n0 + 8 * tx;
    float bs8[8];
    #pragma unroll
    for (int j = 0; j < 8; j++) bs8[j] = bp[j];
    #pragma unroll
    for (int i = 0; i < 8; i++) {
        int t = t0 + 8 * ty + i;
        float* orow = out + ((size_t)b * S + t) * 256 + n0 + 8 * tx;
        float o[8];
        #pragma unroll
        for (int j = 0; j < 4; j++) { U64F2 c; c.u = acc[i][j]; o[2*j] = c.f.x; o[2*j+1] = c.f.y; }
        #pragma unroll
        for (int j = 0; j < 8; j++) o[j] = fmaxf(o[j] + bs8[j], 0.f);
        *(float4*)(orow)     = make_float4(o[0], o[1], o[2], o[3]);
        *(float4*)(orow + 4) = make_float4(o[4], o[5], o[6], o[7]);
    }
}

__global__ void ln_kernel(float* __restrict__ h, const float* __restrict__ sc,
                          const float* __restrict__ bi, int ntok)
{
    int w = threadIdx.x >> 5, lane = threadIdx.x & 31;
    int t = blockIdx.x * 8 + w;
    if (t >= ntok) return;
    float* row = h + (size_t)t * 256;
    float4 v0 = *(float4*)(row + lane * 4);
    float4 v1 = *(float4*)(row + 128 + lane * 4);
    float s = v0.x + v0.y + v0.z + v0.w + v1.x + v1.y + v1.z + v1.w;
    float q = v0.x*v0.x + v0.y*v0.y + v0.z*v0.z + v0.w*v0.w
            + v1.x*v1.x + v1.y*v1.y + v1.z*v1.z + v1.w*v1.w;
    #pragma unroll
    for (int o = 16; o; o >>= 1) {
        s += __shfl_xor_sync(0xffffffffu, s, o);
        q += __shfl_xor_sync(0xffffffffu, q, o);
    }
    float m = s * (1.f / 256.f);
    float r = rsqrtf(q * (1.f / 256.f) - m * m + 1e-5f);
    int f0 = lane * 4, f1 = 128 + lane * 4;
    float4 s0 = *(const float4*)(sc + f0), s1 = *(const float4*)(sc + f1);
    float4 b0 = *(const float4*)(bi + f0), b1 = *(const float4*)(bi + f1);
    v0.x = (v0.x - m)*r*s0.x + b0.x;  v0.y = (v0.y - m)*r*s0.y + b0.y;
    v0.z = (v0.z - m)*r*s0.z + b0.z;  v0.w = (v0.w - m)*r*s0.w + b0.w;
    v1.x = (v1.x - m)*r*s1.x + b1.x;  v1.y = (v1.y - m)*r*s1.y + b1.y;
    v1.z = (v1.z - m)*r*s1.z + b1.z;  v1.w = (v1.w - m)*r*s1.w + b1.w;
    *(float4*)(row + lane * 4)       = v0;
    *(float4*)(row + 128 + lane * 4) = v1;
}

__global__ void dur_final_kernel(const float* __restrict__ h, const float* __restrict__ lw,
                                 const float* __restrict__ lb,
                                 const unsigned char* __restrict__ mask,
                                 const int* __restrict__ scale,
                                 float* __restrict__ out, int ntok)
{
    int w = threadIdx.x >> 5, lane = threadIdx.x & 31;
    int t = blockIdx.x * 8 + w;
    if (t >= ntok) return;
    const float* row = h + (size_t)t * 256;
    float4 v0 = *(const float4*)(row + lane * 4);
    float4 v1 = *(const float4*)(row + 128 + lane * 4);
    float4 w0 = *(const float4*)(lw + lane * 4);
    float4 w1 = *(const float4*)(lw + 128 + lane * 4);
    float d = v0.x*w0.x + v0.y*w0.y + v0.z*w0.z + v0.w*w0.w
            + v1.x*w1.x + v1.y*w1.y + v1.z*w1.z + v1.w*w1.w;
    #pragma unroll
    for (int o = 16; o; o >>= 1) d += __shfl_xor_sync(0xffffffffu, d, o);
    if (lane == 0) {
        float val = d + lb[0];
        if (mask[t]) val = 0.f;
        out[t] = fmaxf(rintf(expf(val) * (float)(*scale)), 0.f);
    }
}

// ==================================================================
// cumsum / length-regulate / embedding add
// ==================================================================
__global__ void cumsum_kernel(const int* __restrict__ dur, int* __restrict__ cs)
{
    __shared__ int s[512];
    int b = blockIdx.x, t = threadIdx.x;
    s[t] = dur[b * 512 + t];
    __syncthreads();
    for (int off = 1; off < 512; off <<= 1) {
        int v = (t >= off) ? s[t - off] : 0;
        __syncthreads();
        s[t] += v;
        __syncthreads();
    }
    cs[b * 512 + t] = s[t];
}

__global__ void length_reg_kernel(const float* __restrict__ hidden,
                                  const int* __restrict__ cs,
                                  float* __restrict__ X,
                                  bf16* __restrict__ Xhi, bf16* __restrict__ Xlo)
{
    __shared__ int scs[512];
    int tid = threadIdx.x;
    int base = blockIdx.x * 4;
    int b    = base >> 12;
    int tloc = base & 4095;
    const int* csb = cs + b * 512;
    scs[tid] = csb[tid];
    scs[tid + 256] = csb[tid + 256];
    __syncthreads();
    int g = tid >> 6, lane = tid & 63;
    int t = tloc + g;
    int lo = 0, hi = 512;
    while (lo < hi) { int mid = (lo + hi) >> 1; if (scs[mid] <= t) lo = mid + 1; else hi = mid; }
    int idx = lo < 512 ? lo : 511;
    bool valid = t < scs[511];
    float4 v = make_float4(0.f, 0.f, 0.f, 0.f);
    if (valid) v = *(const float4*)(hidden + ((size_t)b * 512 + idx) * 256 + lane * 4);
    size_t off = ((size_t)b * 4096 + t) * 256 + lane * 4;
    *(float4*)(X + off) = v;
    float hx = bf16_round(v.x), hy = bf16_round(v.y);
    float hz = bf16_round(v.z), hw = bf16_round(v.w);
    *(uint2*)(Xhi + off) = make_uint2(pack2(hx, hy), pack2(hz, hw));
    *(uint2*)(Xlo + off) = make_uint2(pack2(v.x - hx, v.y - hy), pack2(v.z - hz, v.w - hw));
}

__global__ void add_emb_kernel(const float* __restrict__ X, const float* __restrict__ tgt,
                               const float* __restrict__ bins, const float* __restrict__ emb,
                               float* __restrict__ outp,
                               bf16* __restrict__ Xhi, bf16* __restrict__ Xlo, int wxb)
{
    __shared__ float sb[256];
    int tid = threadIdx.x;
    sb[tid] = bins[tid];
    __syncthreads();
    int base = blockIdx.x * 4;
    int g = tid >> 6, lane = tid & 63;
    int t = base + g;
    float v = tgt[t];
    int lo = 0, hi = 256;
    while (lo < hi) { int mid = (lo + hi) >> 1; if (sb[mid] < v) lo = mid + 1; else hi = mid; }
    int idx = lo < 256 ? lo : 255;
    size_t off = (size_t)t * 256 + lane * 4;
    float4 a = *(const float4*)(X + off);
    float4 e = *(const float4*)(emb + (size_t)idx * 256 + lane * 4);
    a.x += e.x; a.y += e.y; a.z += e.z; a.w += e.w;
    *(float4*)(outp + off) = a;
    if (wxb) {
        float hx = bf16_round(a.x), hy = bf16_round(a.y);
        float hz = bf16_round(a.z), hw = bf16_round(a.w);
        *(uint2*)(Xhi + off) = make_uint2(pack2(hx, hy), pack2(hz, hw));
        *(uint2*)(Xlo + off) = make_uint2(pack2(a.x - hx, a.y - hy), pack2(a.z - hz, a.w - hw));
    }
}

// ==================================================================
// launch
// ==================================================================
extern "C" void kernel_launch(void* const* d_in, const int* in_sizes, int n_in,
                              void* d_out, int out_size)
{
    const float*         hidden    = (const float*)d_in[0];
    const unsigned char* mask      = (const unsigned char*)d_in[1];
    const unsigned char* fmask     = (const unsigned char*)d_in[2];
    const int*           dur_tgt   = (const int*)d_in[3];
    const float*         pitch_tgt = (const float*)d_in[4];
    const float*         energy_tgt= (const float*)d_in[5];
    const int*           dscale    = (const int*)d_in[6];
    const float*         w1        = (const float*)d_in[7];
    const float*         b1        = (const float*)d_in[8];
    const float*         l1s       = (const float*)d_in[9];
    const float*         l1b       = (const float*)d_in[10];
    const float*         w2        = (const float*)d_in[11];
    const float*         b2        = (const float*)d_in[12];
    const float*         l2s       = (const float*)d_in[13];
    const float*         l2b       = (const float*)d_in[14];
    const float*         lw        = (const float*)d_in[15];
    const float*         lb        = (const float*)d_in[16];
    const float*         pbins     = (const float*)d_in[17];
    const float*         pemb      = (const float*)d_in[18];
    const float*         ebins     = (const float*)d_in[19];
    const float*         eemb      = (const float*)d_in[20];

    cudaFuncSetAttribute(hmma_conv_sp, cudaFuncAttributeMaxDynamicSharedMemorySize, 2 * HSTG);

    float* X;  bf16 *Xhi, *Xlo, *H1hi, *H1lo, *H2hi, *H2lo, *Wsp;
    float *H1, *H2;  int* cs;
    cudaGetSymbolAddress((void**)&X,    g_X);
    cudaGetSymbolAddress((void**)&Xhi,  g_Xhi);
    cudaGetSymbolAddress((void**)&Xlo,  g_Xlo);
    cudaGetSymbolAddress((void**)&H1hi, g_H1hi);
    cudaGetSymbolAddress((void**)&H1lo, g_H1lo);
    cudaGetSymbolAddress((void**)&H2hi, g_H2hi);
    cudaGetSymbolAddress((void**)&H2lo, g_H2lo);
    cudaGetSymbolAddress((void**)&H1,   g_H1);
    cudaGetSymbolAddress((void**)&H2,   g_H2);
    cudaGetSymbolAddress((void**)&cs,   g_cs);
    cudaGetSymbolAddress((void**)&Wsp,  g_Wsp);

    float* out_rd     = (float*)d_out;
    float* out_pitch  = out_rd + 32 * 512;
    float* out_energy = out_pitch + 32 * 4096;
    float* out_ve     = out_energy + 32 * 4096;

    repack_w_sp<<<9216, 256>>>(w1, w2);

    // ---- duration predictor (fp32 exact; S=512, 16384 tokens) ----
    {
        dim3 g(16384 / 128, 2);
        conv_gemm_kernel<<<g, 256>>>(hidden, w1, b1, H1, 512);
        ln_kernel<<<16384 / 8, 256>>>(H1, l1s, l1b, 16384);
        conv_gemm_kernel<<<g, 256>>>(H1, w2, b2, H2, 512);
        ln_kernel<<<16384 / 8, 256>>>(H2, l2s, l2b, 16384);
        dur_final_kernel<<<16384 / 8, 256>>>(H2, lw, lb, mask, dscale, out_rd, 16384);
    }

    // ---- length regulate ----
    cumsum_kernel<<<32, 512>>>(dur_tgt, cs);
    length_reg_kernel<<<32 * 4096 / 4, 256>>>(hidden, cs, X, Xhi, Xlo);

    const int NT = 131072;
    dim3 gg(NT / 128, 2);

    // ---- pitch predictor (split-bf16 HMMA) ----
    hmma_conv_sp<<<gg, 256, 2 * HSTG>>>(Xhi,  Xlo,  Wsp + 0 * 589824, b1 + 256, H1hi, H1lo, 4096);
    ln_pair_kernel<<<NT / 8, 256>>>(H1hi, H1lo, l1s + 256, l1b + 256, NT);
    hmma_conv_sp<<<gg, 256, 2 * HSTG>>>(H1hi, H1lo, Wsp + 1 * 589824, b2 + 256, H2hi, H2lo, 4096);
    lnlin_pair_kernel<<<NT / 8, 256>>>(H2hi, H2lo, l2s + 256, l2b + 256,
                                       lw + 256, lb + 1, fmask, out_pitch, NT);
    add_emb_kernel<<<NT / 4, 256>>>(X, pitch_tgt, pbins, pemb, X, Xhi, Xlo, 1);

    // ---- energy predictor (split-bf16 HMMA) ----
    hmma_conv_sp<<<gg, 256, 2 * HSTG>>>(Xhi,  Xlo,  Wsp + 2 * 589824, b1 + 512, H1hi, H1lo, 4096);
    ln_pair_kernel<<<NT / 8, 256>>>(H1hi, H1lo, l1s + 512, l1b + 512, NT);
    hmma_conv_sp<<<gg, 256, 2 * HSTG>>>(H1hi, H1lo, Wsp + 3 * 589824, b2 + 512, H2hi, H2lo, 4096);
    lnlin_pair_kernel<<<NT / 8, 256>>>(H2hi, H2lo, l2s + 512, l2b + 512,
                                       lw + 512, lb + 2, fmask, out_energy, NT);
    add_emb_kernel<<<NT / 4, 256>>>(X, energy_tgt, ebins, eemb, out_ve, nullptr, nullptr, 0);
}